// round 2
// baseline (speedup 1.0000x reference)
#include <cuda_runtime.h>
#include <math.h>
#include <stdint.h>

// Problem dims (fixed by the dataset)
#define B_  8
#define N_  4096
#define C_  1024
#define H_  16
#define D_  64
#define HF_ 2048
#define M_  (B_*N_)   // 32768 rows

// ---------------- scratch (device globals: no allocation allowed) ----------------
__device__ float g_h [(size_t)M_*C_];   // ln1 output
__device__ float g_q [(size_t)M_*C_];
__device__ float g_k [(size_t)M_*C_];
__device__ float g_v [(size_t)M_*C_];
__device__ float g_o [(size_t)M_*C_];   // merged (scrambled) attention output
__device__ float g_x1[(size_t)M_*C_];   // x after first residual
__device__ float g_h2[(size_t)M_*C_];   // ln2 output
__device__ float g_ff[(size_t)M_*HF_];  // gelu(fc1) output

// ---------------- f32x2 packed-FMA helpers (sm_103a) ----------------
__device__ __forceinline__ unsigned long long pack2(float lo, float hi) {
    unsigned long long r;
    asm("mov.b64 %0, {%1, %2};" : "=l"(r) : "f"(lo), "f"(hi));
    return r;
}
__device__ __forceinline__ void fma2(unsigned long long& c, unsigned long long a,
                                     unsigned long long b) {
    asm("fma.rn.f32x2 %0, %1, %2, %0;" : "+l"(c) : "l"(a), "l"(b));
}
__device__ __forceinline__ float2 unpack2(unsigned long long p) {
    float2 r;
    asm("mov.b64 {%0, %1}, %2;" : "=f"(r.x), "=f"(r.y) : "l"(p));
    return r;
}

// ---------------- LayerNorm: one block per row of 1024 ----------------
__global__ void __launch_bounds__(256) ln_kernel(const float* __restrict__ x,
                                                 const float* __restrict__ g,
                                                 const float* __restrict__ b,
                                                 float* __restrict__ out) {
    const size_t row = blockIdx.x;
    const int t = threadIdx.x;
    float4 v = ((const float4*)(x + row * C_))[t];

    float s  = v.x + v.y + v.z + v.w;
    float sq = v.x * v.x + v.y * v.y + v.z * v.z + v.w * v.w;
    #pragma unroll
    for (int o = 16; o; o >>= 1) {
        s  += __shfl_xor_sync(0xffffffffu, s, o);
        sq += __shfl_xor_sync(0xffffffffu, sq, o);
    }
    __shared__ float ss[8], ssq[8];
    if ((t & 31) == 0) { ss[t >> 5] = s; ssq[t >> 5] = sq; }
    __syncthreads();
    s = 0.f; sq = 0.f;
    #pragma unroll
    for (int i = 0; i < 8; i++) { s += ss[i]; sq += ssq[i]; }

    const float mu  = s * (1.0f / C_);
    const float var = sq * (1.0f / C_) - mu * mu;
    const float rs  = rsqrtf(var + 1e-5f);

    float4 gg = ((const float4*)g)[t];
    float4 bb = ((const float4*)b)[t];
    float4 o4;
    o4.x = (v.x - mu) * rs * gg.x + bb.x;
    o4.y = (v.y - mu) * rs * gg.y + bb.y;
    o4.z = (v.z - mu) * rs * gg.z + bb.z;
    o4.w = (v.w - mu) * rs * gg.w + bb.w;
    ((float4*)(out + row * C_))[t] = o4;
}

// ---------------- SGEMM: C = A(MxK) @ W(KxN) with fused epilogues ----------------
// EPI: 0 = none, 1 = +bias +residual, 2 = +bias then exact GELU
// 128x128 block tile, BK=16, 256 threads, 8x8 per thread, f32x2 packed FMA.
template <int EPI>
__global__ void __launch_bounds__(256) gemm_kernel(const float* __restrict__ A,
                                                   const float* __restrict__ W,
                                                   const float* __restrict__ bias,
                                                   const float* __restrict__ resid,
                                                   float* __restrict__ out,
                                                   int Kdim, int Ndim) {
    __shared__ float As[16][128];
    __shared__ float Ws[16][128];
    const int t  = threadIdx.x;
    const int tx = t & 15, ty = t >> 4;
    const int bm = blockIdx.y << 7;
    const int bn = blockIdx.x << 7;

    unsigned long long acc[8][4];
    #pragma unroll
    for (int i = 0; i < 8; i++)
        #pragma unroll
        for (int j = 0; j < 4; j++) acc[i][j] = 0ull;

    const float* Ab = A + (size_t)bm * Kdim;
    const float* Wb = W + bn;

    for (int k0 = 0; k0 < Kdim; k0 += 16) {
        #pragma unroll
        for (int l = 0; l < 2; l++) {
            int i  = t + l * 256;
            int r  = i >> 2, c4 = (i & 3) << 2;
            float4 va = *(const float4*)(Ab + (size_t)r * Kdim + k0 + c4);
            As[c4 + 0][r] = va.x; As[c4 + 1][r] = va.y;
            As[c4 + 2][r] = va.z; As[c4 + 3][r] = va.w;
            int wr = i >> 5, wc = (i & 31) << 2;
            *(float4*)&Ws[wr][wc] = *(const float4*)(Wb + (size_t)(k0 + wr) * Ndim + wc);
        }
        __syncthreads();
        #pragma unroll
        for (int k = 0; k < 16; k++) {
            float a[8], bvals[8];
            *(float4*)(a)         = *(const float4*)&As[k][ty * 8];
            *(float4*)(a + 4)     = *(const float4*)&As[k][ty * 8 + 4];
            *(float4*)(bvals)     = *(const float4*)&Ws[k][tx * 8];
            *(float4*)(bvals + 4) = *(const float4*)&Ws[k][tx * 8 + 4];
            unsigned long long bp[4];
            #pragma unroll
            for (int j = 0; j < 4; j++) bp[j] = pack2(bvals[2 * j], bvals[2 * j + 1]);
            #pragma unroll
            for (int i = 0; i < 8; i++) {
                unsigned long long ap = pack2(a[i], a[i]);
                #pragma unroll
                for (int j = 0; j < 4; j++) fma2(acc[i][j], ap, bp[j]);
            }
        }
        __syncthreads();
    }

    float bv[8];
    if (EPI != 0) {
        *(float4*)(bv)     = *(const float4*)(bias + bn + tx * 8);
        *(float4*)(bv + 4) = *(const float4*)(bias + bn + tx * 8 + 4);
    }
    #pragma unroll
    for (int i = 0; i < 8; i++) {
        const size_t r = (size_t)(bm + ty * 8 + i);
        float vals[8];
        #pragma unroll
        for (int j = 0; j < 4; j++) {
            float2 p = unpack2(acc[i][j]);
            vals[2 * j] = p.x; vals[2 * j + 1] = p.y;
        }
        if (EPI == 1) {
            float4 r0 = *(const float4*)(resid + r * Ndim + bn + tx * 8);
            float4 r1 = *(const float4*)(resid + r * Ndim + bn + tx * 8 + 4);
            vals[0] += bv[0] + r0.x; vals[1] += bv[1] + r0.y;
            vals[2] += bv[2] + r0.z; vals[3] += bv[3] + r0.w;
            vals[4] += bv[4] + r1.x; vals[5] += bv[5] + r1.y;
            vals[6] += bv[6] + r1.z; vals[7] += bv[7] + r1.w;
        } else if (EPI == 2) {
            #pragma unroll
            for (int jj = 0; jj < 8; jj++) {
                float xg = vals[jj] + bv[jj];
                vals[jj] = 0.5f * xg * (1.0f + erff(xg * 0.70710678118654752f));
            }
        }
        float* op = out + r * Ndim + bn + tx * 8;
        *(float4*)(op)     = make_float4(vals[0], vals[1], vals[2], vals[3]);
        *(float4*)(op + 4) = make_float4(vals[4], vals[5], vals[6], vals[7]);
    }
}

// ---------------- Fused attention: one block per (b, h) ----------------
// scores S[e][f] = sum_n q[e,n] k[f,n] * scale ; softmax over f ;
// o[e][n] = sum_f S[e][f] v[f][n] ; written in the SCRAMBLED merge layout:
//   o_merged[b, e*64 + h*4 + (n>>10), n&1023] = o[b,h,e,n]
// (reference does transpose(0,2,1,3).reshape on a (B,H,d,N) tensor).
__global__ void __launch_bounds__(256) attn_kernel(const float* __restrict__ q,
                                                   const float* __restrict__ k,
                                                   const float* __restrict__ v,
                                                   float* __restrict__ o) {
    extern __shared__ float sm[];
    float* S  = sm;                         // 64 * 64
    float* b0 = sm + 64 * 64;               // 64 * 68
    float* b1 = sm + 64 * 64 + 64 * 68;     // 64 * 68

    const int bh = blockIdx.x;
    const int b = bh >> 4, h = bh & 15;
    const size_t qkvbase = (size_t)b * ((size_t)N_ * C_) + (size_t)h * 64;
    const int t  = threadIdx.x;
    const int tx = t & 15, ty = t >> 4;

    float acc[4][4];
    #pragma unroll
    for (int i = 0; i < 4; i++)
        #pragma unroll
        for (int j = 0; j < 4; j++) acc[i][j] = 0.f;

    // -------- phase 1: scores over N --------
    for (int n0 = 0; n0 < N_; n0 += 64) {
        #pragma unroll
        for (int l = 0; l < 4; l++) {
            int i = t + l * 256;
            int nn = i >> 4, e4 = (i & 15) << 2;
            size_t ga = qkvbase + (size_t)(n0 + nn) * C_ + e4;
            *(float4*)&b0[nn * 68 + e4] = *(const float4*)(q + ga);
            *(float4*)&b1[nn * 68 + e4] = *(const float4*)(k + ga);
        }
        __syncthreads();
        #pragma unroll 8
        for (int nn = 0; nn < 64; nn++) {
            float qa[4], kb[4];
            *(float4*)qa = *(const float4*)&b0[nn * 68 + ty * 4];
            *(float4*)kb = *(const float4*)&b1[nn * 68 + tx * 4];
            #pragma unroll
            for (int i = 0; i < 4; i++)
                #pragma unroll
                for (int j = 0; j < 4; j++)
                    acc[i][j] = fmaf(qa[i], kb[j], acc[i][j]);
        }
        __syncthreads();
    }
    #pragma unroll
    for (int i = 0; i < 4; i++)
        #pragma unroll
        for (int j = 0; j < 4; j++)
            S[(ty * 4 + i) * 64 + tx * 4 + j] = acc[i][j] * 0.125f;  // d^-0.5
    __syncthreads();

    // -------- phase 2: softmax over f (rows of S) --------
    if (t < 64) {
        float* Sr = S + t * 64;
        float mx = Sr[0];
        for (int f = 1; f < 64; f++) mx = fmaxf(mx, Sr[f]);
        float sum = 0.f;
        for (int f = 0; f < 64; f++) { float e = expf(Sr[f] - mx); Sr[f] = e; sum += e; }
        float inv = 1.f / sum;
        for (int f = 0; f < 64; f++) Sr[f] *= inv;
    }
    __syncthreads();

    // -------- phase 3: o = S @ v, write scrambled merge layout --------
    for (int n0 = 0; n0 < N_; n0 += 64) {
        #pragma unroll
        for (int l = 0; l < 4; l++) {
            int i = t + l * 256;
            int nn = i >> 4, f4 = (i & 15) << 2;
            float4 rv = *(const float4*)(v + qkvbase + (size_t)(n0 + nn) * C_ + f4);
            b0[(f4 + 0) * 68 + nn] = rv.x;   // store transposed: [f][nn]
            b0[(f4 + 1) * 68 + nn] = rv.y;
            b0[(f4 + 2) * 68 + nn] = rv.z;
            b0[(f4 + 3) * 68 + nn] = rv.w;
        }
        __syncthreads();
        float oacc[4][4];
        #pragma unroll
        for (int i = 0; i < 4; i++)
            #pragma unroll
            for (int j = 0; j < 4; j++) oacc[i][j] = 0.f;
        #pragma unroll 8
        for (int f = 0; f < 64; f++) {
            float vb[4];
            *(float4*)vb = *(const float4*)&b0[f * 68 + tx * 4];
            float sa[4];
            #pragma unroll
            for (int i = 0; i < 4; i++) sa[i] = S[(ty * 4 + i) * 64 + f];
            #pragma unroll
            for (int i = 0; i < 4; i++)
                #pragma unroll
                for (int j = 0; j < 4; j++)
                    oacc[i][j] = fmaf(sa[i], vb[j], oacc[i][j]);
        }
        #pragma unroll
        for (int i = 0; i < 4; i++)
            #pragma unroll
            for (int j = 0; j < 4; j++)
                b1[(ty * 4 + i) * 68 + tx * 4 + j] = oacc[i][j];   // ot[e][nn]
        __syncthreads();
        const size_t obase = (size_t)b * ((size_t)N_ * C_) +
                             (size_t)(h * 4 + (n0 >> 10)) * C_ + (n0 & 1023);
        #pragma unroll
        for (int l = 0; l < 4; l++) {
            int i = t + l * 256;
            int e = i >> 4, n4 = (i & 15) << 2;
            *(float4*)(o + obase + (size_t)e * 64 * C_ + n4) =
                *(const float4*)&b1[e * 68 + n4];
        }
        __syncthreads();
    }
}

// ---------------- launch ----------------
extern "C" void kernel_launch(void* const* d_in, const int* in_sizes, int n_in,
                              void* d_out, int out_size) {
    const float* x      = (const float*)d_in[0];
    const float* ln1_g  = (const float*)d_in[1];
    const float* ln1_b  = (const float*)d_in[2];
    const float* ln2_g  = (const float*)d_in[3];
    const float* ln2_b  = (const float*)d_in[4];
    const float* wq     = (const float*)d_in[5];
    const float* wk     = (const float*)d_in[6];
    const float* wv     = (const float*)d_in[7];
    const float* proj_w = (const float*)d_in[8];
    const float* proj_b = (const float*)d_in[9];
    const float* fc1_w  = (const float*)d_in[10];
    const float* fc1_b  = (const float*)d_in[11];
    const float* fc2_w  = (const float*)d_in[12];
    const float* fc2_b  = (const float*)d_in[13];
    float* out = (float*)d_out;

    float *ph, *pq, *pk, *pv, *po, *px1, *ph2, *pff;
    cudaGetSymbolAddress((void**)&ph,  g_h);
    cudaGetSymbolAddress((void**)&pq,  g_q);
    cudaGetSymbolAddress((void**)&pk,  g_k);
    cudaGetSymbolAddress((void**)&pv,  g_v);
    cudaGetSymbolAddress((void**)&po,  g_o);
    cudaGetSymbolAddress((void**)&px1, g_x1);
    cudaGetSymbolAddress((void**)&ph2, g_h2);
    cudaGetSymbolAddress((void**)&pff, g_ff);

    const int attn_smem = (64 * 64 + 2 * 64 * 68) * 4;  // 51200 bytes
    cudaFuncSetAttribute(attn_kernel, cudaFuncAttributeMaxDynamicSharedMemorySize,
                         attn_smem);

    // h = LN1(x)
    ln_kernel<<<M_, 256>>>(x, ln1_g, ln1_b, ph);
    // q,k,v = h @ w{q,k,v}
    gemm_kernel<0><<<dim3(C_ / 128, M_ / 128), 256>>>(ph, wq, nullptr, nullptr, pq, C_, C_);
    gemm_kernel<0><<<dim3(C_ / 128, M_ / 128), 256>>>(ph, wk, nullptr, nullptr, pk, C_, C_);
    gemm_kernel<0><<<dim3(C_ / 128, M_ / 128), 256>>>(ph, wv, nullptr, nullptr, pv, C_, C_);
    // attention (head-dim attention, scrambled merge)
    attn_kernel<<<B_ * H_, 256, attn_smem>>>(pq, pk, pv, po);
    // x1 = x + o @ proj_w + proj_b
    gemm_kernel<1><<<dim3(C_ / 128, M_ / 128), 256>>>(po, proj_w, proj_b, x, px1, C_, C_);
    // h2 = LN2(x1)
    ln_kernel<<<M_, 256>>>(px1, ln2_g, ln2_b, ph2);
    // ff = gelu(h2 @ fc1_w + fc1_b)
    gemm_kernel<2><<<dim3(HF_ / 128, M_ / 128), 256>>>(ph2, fc1_w, fc1_b, nullptr, pff, C_, HF_);
    // out = x1 + ff @ fc2_w + fc2_b
    gemm_kernel<1><<<dim3(C_ / 128, M_ / 128), 256>>>(pff, fc2_w, fc2_b, px1, out, HF_, C_);
}

// round 5
// speedup vs baseline: 6.0543x; 6.0543x over previous
#include <cuda_runtime.h>
#include <cuda_fp16.h>
#include <math.h>
#include <stdint.h>

#define B_  8
#define N_  4096
#define C_  1024
#define H_  16
#define HF_ 2048
#define M_  (B_*N_)   // 32768

// ---------------- scratch (device globals) ----------------
__device__ __half g_h  [(size_t)M_*C_];                       // ln1 out (fp16)
__device__ float  g_q  [(size_t)M_*C_], g_k[(size_t)M_*C_], g_v[(size_t)M_*C_];
__device__ __half g_o  [(size_t)M_*C_];                       // scrambled attn out (fp16)
__device__ float  g_x1 [(size_t)M_*C_];                       // x + proj (fp32)
__device__ __half g_h2 [(size_t)M_*C_];                       // ln2 out (fp16)
__device__ __half g_ff [(size_t)M_*HF_];                      // gelu(fc1) (fp16)
// transposed fp16 weights, [N,K] row-major (K contiguous)
__device__ __half g_wq[C_*C_], g_wk[C_*C_], g_wv[C_*C_], g_wp[C_*C_];
__device__ __half g_w1[(size_t)C_*HF_];   // [HF, C]
__device__ __half g_w2[(size_t)C_*HF_];   // [C, HF]

// ---------------- PTX helpers (all legal under compute_103) ----------------
#define SWZ(x) ((x) ^ (((x) >> 3) & 0x70))

__device__ __forceinline__ uint32_t s2u(const void* p) {
    uint32_t a;
    asm("{ .reg .u64 t; cvta.to.shared.u64 t, %1; cvt.u32.u64 %0, t; }" : "=r"(a) : "l"(p));
    return a;
}
__device__ __forceinline__ void cpa16(uint32_t d, const void* s) {
    asm volatile("cp.async.cg.shared.global [%0], [%1], 16;" :: "r"(d), "l"(s));
}
__device__ __forceinline__ void cp_commit() { asm volatile("cp.async.commit_group;"); }
__device__ __forceinline__ void cp_wait1()  { asm volatile("cp.async.wait_group 1;"); }
__device__ __forceinline__ void cp_wait0()  { asm volatile("cp.async.wait_group 0;"); }

__device__ __forceinline__ void ldsm_x4(uint32_t* r, uint32_t a) {
    asm volatile("ldmatrix.sync.aligned.m8n8.x4.shared.b16 {%0,%1,%2,%3}, [%4];"
                 : "=r"(r[0]), "=r"(r[1]), "=r"(r[2]), "=r"(r[3]) : "r"(a));
}
__device__ __forceinline__ void ldsm_x2(uint32_t* r, uint32_t a) {
    asm volatile("ldmatrix.sync.aligned.m8n8.x2.shared.b16 {%0,%1}, [%2];"
                 : "=r"(r[0]), "=r"(r[1]) : "r"(a));
}
__device__ __forceinline__ void mma16816(float* c, const uint32_t* a, const uint32_t* b) {
    asm volatile("mma.sync.aligned.m16n8k16.row.col.f32.f16.f16.f32 "
                 "{%0,%1,%2,%3}, {%4,%5,%6,%7}, {%8,%9}, {%0,%1,%2,%3};"
                 : "+f"(c[0]), "+f"(c[1]), "+f"(c[2]), "+f"(c[3])
                 : "r"(a[0]), "r"(a[1]), "r"(a[2]), "r"(a[3]), "r"(b[0]), "r"(b[1]));
}

// ---------------- weight transpose + fp16 convert: W[K,N] -> Wt[N,K] ----------------
__global__ void wtrans(const float* __restrict__ W, int K, int N,
                       __half* __restrict__ Wt) {
    __shared__ float tile[32][33];
    const int n0 = blockIdx.x * 32, k0 = blockIdx.y * 32;
    const int tx = threadIdx.x, ty = threadIdx.y;
    for (int i = ty; i < 32; i += 8)
        tile[i][tx] = W[(size_t)(k0 + i) * N + n0 + tx];
    __syncthreads();
    for (int i = ty; i < 32; i += 8)
        Wt[(size_t)(n0 + i) * K + k0 + tx] = __float2half_rn(tile[tx][i]);
}

// ---------------- LayerNorm (fp32 in, fp16 out) ----------------
__global__ void __launch_bounds__(256) ln_half(const float* __restrict__ x,
                                               const float* __restrict__ g,
                                               const float* __restrict__ b,
                                               __half* __restrict__ out) {
    const size_t row = blockIdx.x;
    const int t = threadIdx.x;
    float4 v = ((const float4*)(x + row * C_))[t];

    float s  = v.x + v.y + v.z + v.w;
    float sq = v.x * v.x + v.y * v.y + v.z * v.z + v.w * v.w;
    #pragma unroll
    for (int o = 16; o; o >>= 1) {
        s  += __shfl_xor_sync(0xffffffffu, s, o);
        sq += __shfl_xor_sync(0xffffffffu, sq, o);
    }
    __shared__ float ss[8], ssq[8];
    if ((t & 31) == 0) { ss[t >> 5] = s; ssq[t >> 5] = sq; }
    __syncthreads();
    s = 0.f; sq = 0.f;
    #pragma unroll
    for (int i = 0; i < 8; i++) { s += ss[i]; sq += ssq[i]; }

    const float mu  = s * (1.0f / C_);
    const float var = sq * (1.0f / C_) - mu * mu;
    const float rs  = rsqrtf(var + 1e-5f);

    float4 gg = ((const float4*)g)[t];
    float4 bb = ((const float4*)b)[t];
    __half2 h01 = __floats2half2_rn((v.x - mu) * rs * gg.x + bb.x,
                                    (v.y - mu) * rs * gg.y + bb.y);
    __half2 h23 = __floats2half2_rn((v.z - mu) * rs * gg.z + bb.z,
                                    (v.w - mu) * rs * gg.w + bb.w);
    uint2 pk; pk.x = *(uint32_t*)&h01; pk.y = *(uint32_t*)&h23;
    *(uint2*)(out + row * C_ + t * 4) = pk;
}

// ---------------- HMMA GEMM: D[M,N] = A[M,K](fp16) @ Wt[N,K]^T + epilogue -------------
// 128x128 tile, BK=64, 8 warps (warp tile 64x32), double-buffered cp.async.
// EPI: 0 = fp32 out; 1 = +bias +resid, fp32 out; 2 = +bias, exact GELU, fp16 out.
template <int EPI>
__global__ void __launch_bounds__(256) hgemm(const __half* __restrict__ A,
                                             const __half* __restrict__ Bt,
                                             const float* __restrict__ bias,
                                             const float* __restrict__ resid,
                                             float* __restrict__ outF,
                                             __half* __restrict__ outH,
                                             int K, int N) {
    extern __shared__ char smem[];
    const uint32_t sb = s2u(smem);

    const int t = threadIdx.x;
    const int lane = t & 31, wid = t >> 5;
    const int wm = wid & 1, wn = wid >> 1;     // warp grid 2(m) x 4(n)
    const int bm = blockIdx.y << 7;
    const int bn = blockIdx.x << 7;
    const int NK = K >> 6;

    float acc[4][4][4];
    #pragma unroll
    for (int i = 0; i < 4; i++)
        #pragma unroll
        for (int j = 0; j < 4; j++)
            #pragma unroll
            for (int e = 0; e < 4; e++) acc[i][j][e] = 0.f;

    auto fill = [&](int stage, int k0) {
        const uint32_t base = sb + stage * 32768;
        #pragma unroll
        for (int l = 0; l < 4; l++) {          // A: 128 rows x 8 x 16B
            int idx = t + 256 * l;
            int r = idx >> 3, c = idx & 7;
            cpa16(base + SWZ((uint32_t)(r * 128 + c * 16)),
                  A + (size_t)(bm + r) * K + k0 + c * 8);
        }
        #pragma unroll
        for (int l = 0; l < 4; l++) {          // B: 128 rows x 8 x 16B
            int idx = t + 256 * l;
            int r = idx >> 3, c = idx & 7;
            cpa16(base + 16384 + SWZ((uint32_t)(r * 128 + c * 16)),
                  Bt + (size_t)(bn + r) * K + k0 + c * 8);
        }
        cp_commit();
    };

    fill(0, 0);
    fill(1, 64);

    for (int ch = 0; ch < NK; ch++) {
        const int buf = ch & 1;
        if (ch == NK - 1) cp_wait0(); else cp_wait1();
        __syncthreads();

        const uint32_t aB = sb + buf * 32768;
        const uint32_t bB = aB + 16384;
        #pragma unroll
        for (int ks = 0; ks < 4; ks++) {
            uint32_t afr[4][4], bfr[4][2];
            #pragma unroll
            for (int i = 0; i < 4; i++) {
                uint32_t off = (uint32_t)((wm * 64 + i * 16 + (lane & 15)) * 128 +
                                          ks * 32 + (lane >> 4) * 16);
                ldsm_x4(afr[i], aB + SWZ(off));
            }
            #pragma unroll
            for (int j = 0; j < 4; j++) {
                uint32_t off = (uint32_t)((wn * 32 + j * 8 + (lane & 7)) * 128 +
                                          ks * 32 + ((lane >> 3) & 1) * 16);
                ldsm_x2(bfr[j], bB + SWZ(off));
            }
            #pragma unroll
            for (int i = 0; i < 4; i++)
                #pragma unroll
                for (int j = 0; j < 4; j++)
                    mma16816(acc[i][j], afr[i], bfr[j]);
        }
        __syncthreads();
        if (ch + 2 < NK) fill(buf, (ch + 2) << 6);
    }

    // -------- epilogue: frags -> smem fp32 [128][132] -> coalesced gmem --------
    float* st = (float*)smem;
    #pragma unroll
    for (int i = 0; i < 4; i++) {
        const int r0 = wm * 64 + i * 16 + (lane >> 2);
        #pragma unroll
        for (int j = 0; j < 4; j++) {
            const int c0 = wn * 32 + j * 8 + 2 * (lane & 3);
            st[r0 * 132 + c0]             = acc[i][j][0];
            st[r0 * 132 + c0 + 1]         = acc[i][j][1];
            st[(r0 + 8) * 132 + c0]       = acc[i][j][2];
            st[(r0 + 8) * 132 + c0 + 1]   = acc[i][j][3];
        }
    }
    __syncthreads();
    #pragma unroll
    for (int l = 0; l < 16; l++) {
        int idx = t + 256 * l;
        int row = idx >> 5, c4 = (idx & 31) << 2;
        const float* src = st + row * 132 + c4;
        float v0 = src[0], v1 = src[1], v2 = src[2], v3 = src[3];
        const int col = bn + c4;
        const size_t go = (size_t)(bm + row) * N + col;
        if (EPI == 0) {
            *(float4*)(outF + go) = make_float4(v0, v1, v2, v3);
        } else if (EPI == 1) {
            const float4 bb = *(const float4*)(bias + col);
            const float4 rr = *(const float4*)(resid + go);
            *(float4*)(outF + go) = make_float4(v0 + bb.x + rr.x, v1 + bb.y + rr.y,
                                                v2 + bb.z + rr.z, v3 + bb.w + rr.w);
        } else {
            const float4 bb = *(const float4*)(bias + col);
            float x0 = v0 + bb.x, x1 = v1 + bb.y, x2 = v2 + bb.z, x3 = v3 + bb.w;
            const float ki = 0.70710678118654752f;
            x0 = 0.5f * x0 * (1.0f + erff(x0 * ki));
            x1 = 0.5f * x1 * (1.0f + erff(x1 * ki));
            x2 = 0.5f * x2 * (1.0f + erff(x2 * ki));
            x3 = 0.5f * x3 * (1.0f + erff(x3 * ki));
            __half2 h01 = __floats2half2_rn(x0, x1);
            __half2 h23 = __floats2half2_rn(x2, x3);
            uint2 pk; pk.x = *(uint32_t*)&h01; pk.y = *(uint32_t*)&h23;
            *(uint2*)(outH + go) = pk;
        }
    }
}

// ---------------- fused attention (fp32 in, fp16 scrambled out) ----------------
// o_merged[b, e*64 + h*4 + (n>>10), n&1023] = o[b,h,e,n]
__global__ void __launch_bounds__(256) attn_kernel(const float* __restrict__ q,
                                                   const float* __restrict__ k,
                                                   const float* __restrict__ v,
                                                   __half* __restrict__ o) {
    extern __shared__ float sm[];
    float* S  = sm;                         // 64*64
    float* b0 = sm + 64 * 64;               // 64*68
    float* b1 = sm + 64 * 64 + 64 * 68;     // 64*68

    const int bh = blockIdx.x;
    const int b = bh >> 4, h = bh & 15;
    const size_t qkvbase = (size_t)b * ((size_t)N_ * C_) + (size_t)h * 64;
    const int t  = threadIdx.x;
    const int tx = t & 15, ty = t >> 4;

    float acc[4][4];
    #pragma unroll
    for (int i = 0; i < 4; i++)
        #pragma unroll
        for (int j = 0; j < 4; j++) acc[i][j] = 0.f;

    for (int n0 = 0; n0 < N_; n0 += 64) {
        #pragma unroll
        for (int l = 0; l < 4; l++) {
            int i = t + l * 256;
            int nn = i >> 4, e4 = (i & 15) << 2;
            size_t ga = qkvbase + (size_t)(n0 + nn) * C_ + e4;
            *(float4*)&b0[nn * 68 + e4] = *(const float4*)(q + ga);
            *(float4*)&b1[nn * 68 + e4] = *(const float4*)(k + ga);
        }
        __syncthreads();
        #pragma unroll 8
        for (int nn = 0; nn < 64; nn++) {
            float qa[4], kb[4];
            *(float4*)qa = *(const float4*)&b0[nn * 68 + ty * 4];
            *(float4*)kb = *(const float4*)&b1[nn * 68 + tx * 4];
            #pragma unroll
            for (int i = 0; i < 4; i++)
                #pragma unroll
                for (int j = 0; j < 4; j++)
                    acc[i][j] = fmaf(qa[i], kb[j], acc[i][j]);
        }
        __syncthreads();
    }
    #pragma unroll
    for (int i = 0; i < 4; i++)
        #pragma unroll
        for (int j = 0; j < 4; j++)
            S[(ty * 4 + i) * 64 + tx * 4 + j] = acc[i][j] * 0.125f;
    __syncthreads();

    if (t < 64) {
        float* Sr = S + t * 64;
        float mx = Sr[0];
        for (int f = 1; f < 64; f++) mx = fmaxf(mx, Sr[f]);
        float sum = 0.f;
        for (int f = 0; f < 64; f++) { float e = expf(Sr[f] - mx); Sr[f] = e; sum += e; }
        float inv = 1.f / sum;
        for (int f = 0; f < 64; f++) Sr[f] *= inv;
    }
    __syncthreads();

    for (int n0 = 0; n0 < N_; n0 += 64) {
        #pragma unroll
        for (int l = 0; l < 4; l++) {
            int i = t + l * 256;
            int nn = i >> 4, f4 = (i & 15) << 2;
            float4 rv = *(const float4*)(v + qkvbase + (size_t)(n0 + nn) * C_ + f4);
            b0[(f4 + 0) * 68 + nn] = rv.x;
            b0[(f4 + 1) * 68 + nn] = rv.y;
            b0[(f4 + 2) * 68 + nn] = rv.z;
            b0[(f4 + 3) * 68 + nn] = rv.w;
        }
        __syncthreads();
        float oacc[4][4];
        #pragma unroll
        for (int i = 0; i < 4; i++)
            #pragma unroll
            for (int j = 0; j < 4; j++) oacc[i][j] = 0.f;
        #pragma unroll 8
        for (int f = 0; f < 64; f++) {
            float vb[4];
            *(float4*)vb = *(const float4*)&b0[f * 68 + tx * 4];
            float sa[4];
            #pragma unroll
            for (int i = 0; i < 4; i++) sa[i] = S[(ty * 4 + i) * 64 + f];
            #pragma unroll
            for (int i = 0; i < 4; i++)
                #pragma unroll
                for (int j = 0; j < 4; j++)
                    oacc[i][j] = fmaf(sa[i], vb[j], oacc[i][j]);
        }
        #pragma unroll
        for (int i = 0; i < 4; i++)
            #pragma unroll
            for (int j = 0; j < 4; j++)
                b1[(ty * 4 + i) * 68 + tx * 4 + j] = oacc[i][j];
        __syncthreads();
        const size_t obase = (size_t)b * ((size_t)N_ * C_) +
                             (size_t)(h * 4 + (n0 >> 10)) * C_ + (n0 & 1023);
        #pragma unroll
        for (int l = 0; l < 4; l++) {
            int i = t + l * 256;
            int e = i >> 4, n4 = (i & 15) << 2;
            float4 vv = *(const float4*)&b1[e * 68 + n4];
            __half2 h01 = __floats2half2_rn(vv.x, vv.y);
            __half2 h23 = __floats2half2_rn(vv.z, vv.w);
            uint2 pk; pk.x = *(uint32_t*)&h01; pk.y = *(uint32_t*)&h23;
            *(uint2*)(o + obase + (size_t)e * 64 * C_ + n4) = pk;
        }
        __syncthreads();
    }
}

// ---------------- launch ----------------
extern "C" void kernel_launch(void* const* d_in, const int* in_sizes, int n_in,
                              void* d_out, int out_size) {
    const float* x      = (const float*)d_in[0];
    const float* ln1_g  = (const float*)d_in[1];
    const float* ln1_b  = (const float*)d_in[2];
    const float* ln2_g  = (const float*)d_in[3];
    const float* ln2_b  = (const float*)d_in[4];
    const float* wq     = (const float*)d_in[5];
    const float* wk     = (const float*)d_in[6];
    const float* wv     = (const float*)d_in[7];
    const float* proj_w = (const float*)d_in[8];
    const float* proj_b = (const float*)d_in[9];
    const float* fc1_w  = (const float*)d_in[10];
    const float* fc1_b  = (const float*)d_in[11];
    const float* fc2_w  = (const float*)d_in[12];
    const float* fc2_b  = (const float*)d_in[13];
    float* out = (float*)d_out;

    __half *ph, *po, *ph2, *pff, *pwq, *pwk, *pwv, *pwp, *pw1, *pw2;
    float *pq, *pk, *pv, *px1;
    cudaGetSymbolAddress((void**)&ph,  g_h);
    cudaGetSymbolAddress((void**)&pq,  g_q);
    cudaGetSymbolAddress((void**)&pk,  g_k);
    cudaGetSymbolAddress((void**)&pv,  g_v);
    cudaGetSymbolAddress((void**)&po,  g_o);
    cudaGetSymbolAddress((void**)&px1, g_x1);
    cudaGetSymbolAddress((void**)&ph2, g_h2);
    cudaGetSymbolAddress((void**)&pff, g_ff);
    cudaGetSymbolAddress((void**)&pwq, g_wq);
    cudaGetSymbolAddress((void**)&pwk, g_wk);
    cudaGetSymbolAddress((void**)&pwv, g_wv);
    cudaGetSymbolAddress((void**)&pwp, g_wp);
    cudaGetSymbolAddress((void**)&pw1, g_w1);
    cudaGetSymbolAddress((void**)&pw2, g_w2);

    const int GEMM_SMEM = 128 * 132 * 4;      // 67584 (> 2*32768 stage area)
    cudaFuncSetAttribute(hgemm<0>, cudaFuncAttributeMaxDynamicSharedMemorySize, GEMM_SMEM);
    cudaFuncSetAttribute(hgemm<1>, cudaFuncAttributeMaxDynamicSharedMemorySize, GEMM_SMEM);
    cudaFuncSetAttribute(hgemm<2>, cudaFuncAttributeMaxDynamicSharedMemorySize, GEMM_SMEM);
    const int ATTN_SMEM = (64 * 64 + 2 * 64 * 68) * 4;
    cudaFuncSetAttribute(attn_kernel, cudaFuncAttributeMaxDynamicSharedMemorySize, ATTN_SMEM);

    dim3 tb32(32, 8);
    wtrans<<<dim3(C_ / 32, C_ / 32), tb32>>>(wq, C_, C_, pwq);
    wtrans<<<dim3(C_ / 32, C_ / 32), tb32>>>(wk, C_, C_, pwk);
    wtrans<<<dim3(C_ / 32, C_ / 32), tb32>>>(wv, C_, C_, pwv);
    wtrans<<<dim3(C_ / 32, C_ / 32), tb32>>>(proj_w, C_, C_, pwp);
    wtrans<<<dim3(HF_ / 32, C_ / 32), tb32>>>(fc1_w, C_, HF_, pw1);   // [HF,C]
    wtrans<<<dim3(C_ / 32, HF_ / 32), tb32>>>(fc2_w, HF_, C_, pw2);   // [C,HF]

    // h = LN1(x) -> fp16
    ln_half<<<M_, 256>>>(x, ln1_g, ln1_b, ph);
    // q,k,v = h @ w{q,k,v} (fp32 out)
    hgemm<0><<<dim3(C_ / 128, M_ / 128), 256, GEMM_SMEM>>>(
        ph, pwq, nullptr, nullptr, pq, nullptr, C_, C_);
    hgemm<0><<<dim3(C_ / 128, M_ / 128), 256, GEMM_SMEM>>>(
        ph, pwk, nullptr, nullptr, pk, nullptr, C_, C_);
    hgemm<0><<<dim3(C_ / 128, M_ / 128), 256, GEMM_SMEM>>>(
        ph, pwv, nullptr, nullptr, pv, nullptr, C_, C_);
    // attention -> scrambled fp16 o
    attn_kernel<<<B_ * H_, 256, ATTN_SMEM>>>(pq, pk, pv, po);
    // x1 = x + o @ proj_w + proj_b
    hgemm<1><<<dim3(C_ / 128, M_ / 128), 256, GEMM_SMEM>>>(
        po, pwp, proj_b, x, px1, nullptr, C_, C_);
    // h2 = LN2(x1) -> fp16
    ln_half<<<M_, 256>>>(px1, ln2_g, ln2_b, ph2);
    // ff = gelu(h2 @ fc1_w + fc1_b) -> fp16
    hgemm<2><<<dim3(HF_ / 128, M_ / 128), 256, GEMM_SMEM>>>(
        ph2, pw1, fc1_b, nullptr, nullptr, pff, C_, HF_);
    // out = x1 + ff @ fc2_w + fc2_b
    hgemm<1><<<dim3(C_ / 128, M_ / 128), 256, GEMM_SMEM>>>(
        pff, pw2, fc2_b, px1, out, nullptr, HF_, C_);
}